// round 7
// baseline (speedup 1.0000x reference)
#include <cuda_runtime.h>

#define HH 384
#define WW 384
#define BB 8
#define CC 4
#define NPIX (HH*WW)        // 147456
#define NINST (BB*CC)       // 32
#define BIGF 1e8f
#define DINF (1 << 28)

#define TW 16               // k_loss tile width
#define NWT (WW / TW)       // 24 strips
#define NBLK (BB * NWT)     // 192 k_loss blocks
#define TILE_ELEMS (CC * HH * TW)   // 24576 floats = 96KB

// Signed row-pass field: w[b][c][h][x] = (t==c) ? -dne^2 (or -BIG) : +deq^2 (or +BIG)
// Decode: d1_eq = max(w,0), d1_ne = max(-w,0). Exact (|w| >= 1 or |w| = 1e8).
__device__ float g_w[(unsigned)NINST * NPIX];   // ~18.9 MB
__device__ float g_part[NBLK];

// ---------------------------------------------------------------------------
// Rare-path exact full-row scan (12 words), optional complement.
__device__ int full_scan(const unsigned* __restrict__ words, int x, bool inv) {
    int w0 = x >> 5, b0 = x & 31;
    unsigned wv = words[w0]; if (inv) wv = ~wv;

    int dl = DINF;
    unsigned curl = wv & (0xFFFFFFFFu >> (31 - b0));
    int wl = w0;
    while (curl == 0 && wl > 0) {
        --wl; unsigned t = words[wl]; if (inv) t = ~t; curl = t;
    }
    if (curl) dl = x - (wl * 32 + (31 - __clz(curl)));

    int dr = DINF;
    unsigned curr = wv & (0xFFFFFFFFu << b0);
    int wr = w0;
    while (curr == 0 && wr < 11) {
        ++wr; unsigned t = words[wr]; if (inv) t = ~t; curr = t;
    }
    if (curr) dr = (wr * 32 + (__ffs(curr) - 1)) - x;

    return min(dl, dr);
}

// 64-bit window of row bits [x-32, x+31] from padded words (Wp[0]=Wp[13]=0).
__device__ __forceinline__ unsigned long long build_win(const unsigned* __restrict__ Wp, int x) {
    int j = x >> 5, sh = x & 31;
    unsigned long long A = (unsigned long long)Wp[j] | ((unsigned long long)Wp[j + 1] << 32);
    unsigned long long B = (unsigned long long)Wp[j + 2];
    return (A >> sh) | ((B << (63 - sh)) << 1);
}

__device__ __forceinline__ unsigned long long edge_mask(int x) {
    unsigned long long vlo = (x >= 32)  ? ~0ull : (~0ull << (32 - x));
    unsigned long long vhi = (x <= 352) ? ~0ull : (~0ull >> (x - 352));
    return vlo & vhi;
}

__device__ __forceinline__ int win_dist(unsigned long long win) {
    unsigned long long lowp  = win & 0x1FFFFFFFFULL;
    unsigned long long highp = win >> 32;
    int dl = lowp  ? (32 - (63 - __clzll(lowp))) : DINF;
    int dr = highp ? (__ffsll(highp) - 1)        : DINF;
    return min(dl, dr);
}

// ---------------------------------------------------------------------------
// Row pass: one block per (b,h) row; 384 threads. Branch-free window scans,
// exact full-scan fallback. 3 eq-scans + 1 complement-scan per pixel.
__global__ void k_rowpass(const int* __restrict__ targets) {
    __shared__ unsigned Wp[CC][14];

    int b = blockIdx.x / HH;
    int h = blockIdx.x % HH;
    int x = threadIdx.x;
    int warp = x >> 5, lane = x & 31;

    int t = targets[(b * HH + h) * WW + x];

#pragma unroll
    for (int c = 0; c < CC; ++c) {
        unsigned m = __ballot_sync(0xFFFFFFFFu, t == c);
        if (lane == 0) Wp[c][warp + 1] = m;
    }
    if (x < CC) { Wp[x][0] = 0; Wp[x][13] = 0; }
    __syncthreads();

    unsigned long long wn = (~build_win(Wp[t], x)) & edge_mask(x);
    int dn = win_dist(wn);
    if (dn >= DINF) dn = full_scan(&Wp[t][1], x, true);
    float w_own = (dn >= DINF) ? -BIGF : -((float)dn * (float)dn);

    unsigned base = (unsigned)(b * CC) * NPIX + h * WW + x;

#pragma unroll
    for (int c = 0; c < CC; ++c) {
        unsigned long long we = build_win(Wp[c], x);
        int de = win_dist(we);
        if (de >= DINF) de = full_scan(&Wp[c][1], x, false);
        float w_eq = (de >= DINF) ? BIGF : ((float)de * (float)de);
        g_w[base + (unsigned)c * NPIX] = (c == t) ? w_own : w_eq;
    }
}

// ---------------------------------------------------------------------------
// Col pass, smem-tiled: block = (batch, 16-wide strip). Loads the full
// [4][384][16] slab of g_w once (coalesced), then the exact early-exit
// vertical min-plus runs entirely in shared memory (conflict-free: a warp
// spans 32 consecutive words at every dh). Softmax + phi + partial sum.
__global__ void __launch_bounds__(512) k_loss(const float* __restrict__ logits) {
    extern __shared__ float tile[];      // [c][h][w] : CC*HH*TW floats (96KB)

    int tid = threadIdx.x;
    int b  = blockIdx.x / NWT;
    int w0 = (blockIdx.x % NWT) * TW;

    // cooperative slab load: each byte of g_w read exactly once, coalesced
#pragma unroll
    for (int k = 0; k < TILE_ELEMS / 512; ++k) {
        int j = tid + k * 512;
        int c = j / (HH * TW);
        int rr = j - c * (HH * TW);
        int h = rr / TW;
        int w = rr - h * TW;
        tile[j] = g_w[(unsigned)(b * CC + c) * NPIX + h * WW + w0 + w];
    }
    __syncthreads();

    float acc = 0.0f;
#pragma unroll 1
    for (int k = 0; k < (HH * TW) / 512; ++k) {       // 12 pixels per thread
        int i = tid + k * 512;
        int h = i / TW;
        int w = i - h * TW;

        int gbase = (b * CC) * NPIX + h * WW + w0 + w;
        float l0 = logits[gbase];
        float l1 = logits[gbase + NPIX];
        float l2 = logits[gbase + 2 * NPIX];
        float l3 = logits[gbase + 3 * NPIX];
        float mx = fmaxf(fmaxf(l0, l1), fmaxf(l2, l3));
        float e0 = __expf(l0 - mx), e1 = __expf(l1 - mx);
        float e2 = __expf(l2 - mx), e3 = __expf(l3 - mx);
        float inv = 1.0f / (e0 + e1 + e2 + e3);
        float pr[4] = { e0 * inv, e1 * inv, e2 * inv, e3 * inv };

#pragma unroll 1
        for (int c = 0; c < CC; ++c) {
            const float* tw = tile + c * (HH * TW) + w;
            float v0 = tw[h * TW];
            float bp = fmaxf(v0, 0.0f);     // pos^2 running min
            float bn = fmaxf(-v0, 0.0f);    // neg^2 running min
            float q = 1.0f, stp = 3.0f;     // q = dh^2
            int hm = h - 1, hp = h + 1;
#pragma unroll 1
            for (int dh = 1; dh < HH; ++dh) {
                if (q >= fmaxf(bp, bn)) break;
                if (hm >= 0) {
                    float v = tw[hm * TW];
                    bp = fminf(bp, fmaxf(v, 0.0f) + q);
                    bn = fminf(bn, fmaxf(-v, 0.0f) + q);
                }
                if (hp < HH) {
                    float v = tw[hp * TW];
                    bp = fminf(bp, fmaxf(v, 0.0f) + q);
                    bn = fminf(bn, fmaxf(-v, 0.0f) + q);
                }
                q += stp; stp += 2.0f;
                --hm; ++hp;
            }
            // Empty/full detection: finite dist^2 <= 2*383^2 ~ 2.9e5 << 1e7;
            // empty-mask surface stays exactly 1e8.
            float phi;
            if (bp >= 1e7f)       phi =  sqrtf(bp);
            else if (bn >= 1e7f)  phi = -sqrtf(bn);
            else                  phi =  sqrtf(bp) - sqrtf(bn) + 1.0f;
            acc += pr[c] * phi;
        }
    }

    // block reduction (fixed shape -> deterministic)
    int lane = tid & 31, wid = tid >> 5;
#pragma unroll
    for (int o = 16; o; o >>= 1) acc += __shfl_down_sync(0xFFFFFFFFu, acc, o);
    __shared__ float sm[16];
    if (lane == 0) sm[wid] = acc;
    __syncthreads();
    if (tid < 16) {
        float v = sm[tid];
#pragma unroll
        for (int o = 8; o; o >>= 1) v += __shfl_down_sync(0x0000FFFFu, v, o);
        if (tid == 0) g_part[blockIdx.x] = v;
    }
}

// ---------------------------------------------------------------------------
// Final reduce over 192 partials: one independent load per thread, add tree.
__global__ void __launch_bounds__(192) k_final(float* __restrict__ out) {
    int t = threadIdx.x;
    float s = g_part[t];

    int lane = t & 31, wid = t >> 5;
#pragma unroll
    for (int o = 16; o; o >>= 1) s += __shfl_down_sync(0xFFFFFFFFu, s, o);
    __shared__ float sm[6];
    if (lane == 0) sm[wid] = s;
    __syncthreads();
    if (t < 6) {
        float v = sm[t];
        v += __shfl_down_sync(0x0000003Fu, v, 4);
        v += __shfl_down_sync(0x0000003Fu, v, 2);
        v += __shfl_down_sync(0x0000003Fu, v, 1);
        if (t == 0)
            out[0] = v * (1.0f / ((float)BB * CC * NPIX));
    }
}

// ---------------------------------------------------------------------------
extern "C" void kernel_launch(void* const* d_in, const int* in_sizes, int n_in,
                              void* d_out, int out_size) {
    const float* logits  = (const float*)d_in[0];
    const int*   targets = (const int*)d_in[1];
    float* out = (float*)d_out;

    cudaFuncSetAttribute(k_loss, cudaFuncAttributeMaxDynamicSharedMemorySize,
                         TILE_ELEMS * (int)sizeof(float));

    k_rowpass<<<BB * HH, 384>>>(targets);
    k_loss<<<NBLK, 512, TILE_ELEMS * sizeof(float)>>>(logits);
    k_final<<<1, 192>>>(out);
}

// round 12
// speedup vs baseline: 1.4464x; 1.4464x over previous
#include <cuda_runtime.h>

#define HH 384
#define WW 384
#define BB 8
#define CC 4
#define NPIX (HH*WW)        // 147456
#define NINST (BB*CC)       // 32
#define BIGF 1e8f
#define NBLK3 4608          // (BB*NPIX)/256 exactly
#define DINF (1 << 28)

// Signed row-pass field: w[b][c][h][x] = (t==c) ? -dne^2 (or -BIG) : +deq^2 (or +BIG)
// Decode: d1_eq = max(w,0), d1_ne = max(-w,0). Exact (|w| >= 1 or |w| = 1e8).
__device__ float g_w[(unsigned)NINST * NPIX];   // ~18.9 MB
__device__ float g_part[NBLK3];

// ---------------------------------------------------------------------------
// Rare-path exact full-row scan (12 words), optional complement.
__device__ int full_scan(const unsigned* __restrict__ words, int x, bool inv) {
    int w0 = x >> 5, b0 = x & 31;
    unsigned wv = words[w0]; if (inv) wv = ~wv;

    int dl = DINF;
    unsigned curl = wv & (0xFFFFFFFFu >> (31 - b0));
    int wl = w0;
    while (curl == 0 && wl > 0) {
        --wl; unsigned t = words[wl]; if (inv) t = ~t; curl = t;
    }
    if (curl) dl = x - (wl * 32 + (31 - __clz(curl)));

    int dr = DINF;
    unsigned curr = wv & (0xFFFFFFFFu << b0);
    int wr = w0;
    while (curr == 0 && wr < 11) {
        ++wr; unsigned t = words[wr]; if (inv) t = ~t; curr = t;
    }
    if (curr) dr = (wr * 32 + (__ffs(curr) - 1)) - x;

    return min(dl, dr);
}

// 64-bit window of row bits [x-32, x+31] from padded words (Wp[0]=Wp[13]=0).
__device__ __forceinline__ unsigned long long build_win(const unsigned* __restrict__ Wp, int x) {
    int j = x >> 5, sh = x & 31;
    unsigned long long A = (unsigned long long)Wp[j] | ((unsigned long long)Wp[j + 1] << 32);
    unsigned long long B = (unsigned long long)Wp[j + 2];
    return (A >> sh) | ((B << (63 - sh)) << 1);
}

__device__ __forceinline__ unsigned long long edge_mask(int x) {
    unsigned long long vlo = (x >= 32)  ? ~0ull : (~0ull << (32 - x));
    unsigned long long vhi = (x <= 352) ? ~0ull : (~0ull >> (x - 352));
    return vlo & vhi;
}

__device__ __forceinline__ int win_dist(unsigned long long win) {
    unsigned long long lowp  = win & 0x1FFFFFFFFULL;
    unsigned long long highp = win >> 32;
    int dl = lowp  ? (32 - (63 - __clzll(lowp))) : DINF;
    int dr = highp ? (__ffsll(highp) - 1)        : DINF;
    return min(dl, dr);
}

// ---------------------------------------------------------------------------
// Row pass: one block per (b,h) row; 384 threads. Branch-free window scans,
// exact full-scan fallback. 3 eq-scans + 1 complement-scan per pixel.
__global__ void k_rowpass(const int* __restrict__ targets) {
    __shared__ unsigned Wp[CC][14];

    int b = blockIdx.x / HH;
    int h = blockIdx.x % HH;
    int x = threadIdx.x;
    int warp = x >> 5, lane = x & 31;

    int t = targets[(b * HH + h) * WW + x];

#pragma unroll
    for (int c = 0; c < CC; ++c) {
        unsigned m = __ballot_sync(0xFFFFFFFFu, t == c);
        if (lane == 0) Wp[c][warp + 1] = m;
    }
    if (x < CC) { Wp[x][0] = 0; Wp[x][13] = 0; }
    __syncthreads();

    unsigned long long wn = (~build_win(Wp[t], x)) & edge_mask(x);
    int dn = win_dist(wn);
    if (dn >= DINF) dn = full_scan(&Wp[t][1], x, true);
    float w_own = (dn >= DINF) ? -BIGF : -((float)dn * (float)dn);

    unsigned base = (unsigned)(b * CC) * NPIX + h * WW + x;

#pragma unroll
    for (int c = 0; c < CC; ++c) {
        unsigned long long we = build_win(Wp[c], x);
        int de = win_dist(we);
        if (de >= DINF) de = full_scan(&Wp[c][1], x, false);
        float w_eq = (de >= DINF) ? BIGF : ((float)de * (float)de);
        g_w[base + (unsigned)c * NPIX] = (c == t) ? w_own : w_eq;
    }
}

// ---------------------------------------------------------------------------
// Col pass. Per class, vertical min-plus with the signed field serving both
// polarities. Structure: dh=0..4 fully unrolled UNCONDITIONAL straight-line
// (9 independent loads per class, 36 per pixel in flight -> one L1 round trip
// instead of a 12-deep serial chain). Extra iterations past the true radius
// are exact no-ops (candidate = v+q >= q >= best). Rare exact tail from dh=5.
__global__ void __launch_bounds__(256) k_loss(const float* __restrict__ logits) {
    int pid = blockIdx.x * 256 + threadIdx.x;     // 0 .. BB*NPIX-1 (exact)
    int b = pid / NPIX;
    int r = pid - b * NPIX;
    int h = r / WW;

    const float* base = g_w + (unsigned)(b * CC) * NPIX + r;

    float bp[CC], bn[CC];
    // ---- batched prologues: all loads independent, max MLP ----
#pragma unroll
    for (int c = 0; c < CC; ++c) {
        const float* pw = base + c * NPIX;
        float v0 = __ldg(pw);
        bp[c] = fmaxf(v0, 0.0f);
        bn[c] = fmaxf(-v0, 0.0f);
#pragma unroll
        for (int dh = 1; dh <= 4; ++dh) {
            float q = (float)(dh * dh);
            if (h >= dh) {
                float v = __ldg(pw - dh * WW);
                bp[c] = fminf(bp[c], fmaxf(v, 0.0f) + q);
                bn[c] = fminf(bn[c], fmaxf(-v, 0.0f) + q);
            }
            if (h + dh < HH) {
                float v = __ldg(pw + dh * WW);
                bp[c] = fminf(bp[c], fmaxf(v, 0.0f) + q);
                bn[c] = fminf(bn[c], fmaxf(-v, 0.0f) + q);
            }
        }
    }

    // ---- rare exact tails ----
#pragma unroll
    for (int c = 0; c < CC; ++c) {
        if (fmaxf(bp[c], bn[c]) > 25.0f) {
            const float* pw = base + c * NPIX;
            float q = 25.0f, stp = 11.0f;      // q = dh^2 at dh=5
            int hm = h - 5, hp = h + 5;
            const float* pm = pw - 5 * WW;
            const float* pq = pw + 5 * WW;
#pragma unroll 1
            for (int dh = 5; dh < HH; ++dh) {
                if (q >= fmaxf(bp[c], bn[c])) break;
                if (hm >= 0) {
                    float v = __ldg(pm);
                    bp[c] = fminf(bp[c], fmaxf(v, 0.0f) + q);
                    bn[c] = fminf(bn[c], fmaxf(-v, 0.0f) + q);
                }
                if (hp < HH) {
                    float v = __ldg(pq);
                    bp[c] = fminf(bp[c], fmaxf(v, 0.0f) + q);
                    bn[c] = fminf(bn[c], fmaxf(-v, 0.0f) + q);
                }
                q += stp; stp += 2.0f;
                pm -= WW; pq += WW; --hm; ++hp;
            }
        }
    }

    // ---- softmax ----
    float l0 = logits[(b * CC + 0) * NPIX + r];
    float l1 = logits[(b * CC + 1) * NPIX + r];
    float l2 = logits[(b * CC + 2) * NPIX + r];
    float l3 = logits[(b * CC + 3) * NPIX + r];
    float mx = fmaxf(fmaxf(l0, l1), fmaxf(l2, l3));
    float e0 = __expf(l0 - mx), e1 = __expf(l1 - mx);
    float e2 = __expf(l2 - mx), e3 = __expf(l3 - mx);
    float inv = 1.0f / (e0 + e1 + e2 + e3);
    float pr[4] = { e0 * inv, e1 * inv, e2 * inv, e3 * inv };

    float acc = 0.0f;
#pragma unroll
    for (int c = 0; c < CC; ++c) {
        // Empty/full detection: finite dist^2 <= 2*383^2 ~ 2.9e5 << 1e7;
        // empty-mask surface stays exactly 1e8.
        float phi;
        if (bp[c] >= 1e7f)       phi =  sqrtf(bp[c]);
        else if (bn[c] >= 1e7f)  phi = -sqrtf(bn[c]);
        else                     phi =  sqrtf(bp[c]) - sqrtf(bn[c]) + 1.0f;
        acc += pr[c] * phi;
    }

    // block reduction (fixed shape -> deterministic)
    int lane = threadIdx.x & 31, wid = threadIdx.x >> 5;
#pragma unroll
    for (int o = 16; o; o >>= 1) acc += __shfl_down_sync(0xFFFFFFFFu, acc, o);
    __shared__ float sm[8];
    if (lane == 0) sm[wid] = acc;
    __syncthreads();
    if (threadIdx.x < 8) {
        float v = sm[threadIdx.x];
#pragma unroll
        for (int o = 4; o; o >>= 1) v += __shfl_down_sync(0x000000FFu, v, o);
        if (threadIdx.x == 0) g_part[blockIdx.x] = v;
    }
}

// ---------------------------------------------------------------------------
// Final reduce: 18 independent loads per thread (MLP), then add tree.
__global__ void __launch_bounds__(256) k_final(float* __restrict__ out) {
    int t = threadIdx.x;
    float a[18];
#pragma unroll
    for (int i = 0; i < 18; ++i) a[i] = g_part[t + i * 256];
    float s = 0.0f;
#pragma unroll
    for (int i = 0; i < 18; ++i) s += a[i];

    int lane = t & 31, wid = t >> 5;
#pragma unroll
    for (int o = 16; o; o >>= 1) s += __shfl_down_sync(0xFFFFFFFFu, s, o);
    __shared__ float sm[8];
    if (lane == 0) sm[wid] = s;
    __syncthreads();
    if (t < 8) {
        float v = sm[t];
#pragma unroll
        for (int o = 4; o; o >>= 1) v += __shfl_down_sync(0x000000FFu, v, o);
        if (t == 0)
            out[0] = v * (1.0f / ((float)BB * CC * NPIX));
    }
}

// ---------------------------------------------------------------------------
extern "C" void kernel_launch(void* const* d_in, const int* in_sizes, int n_in,
                              void* d_out, int out_size) {
    const float* logits  = (const float*)d_in[0];
    const int*   targets = (const int*)d_in[1];
    float* out = (float*)d_out;

    k_rowpass<<<BB * HH, 384>>>(targets);
    k_loss<<<NBLK3, 256>>>(logits);
    k_final<<<1, 256>>>(out);
}